// round 6
// baseline (speedup 1.0000x reference)
#include <cuda_runtime.h>
#include <math.h>
#include <stdint.h>

#define F 256
#define N_MAX 65536
#define E_CAP (1 << 20)
#define SCAN_CHUNK 2048

// Scratch (allocation-free rule: __device__ globals)
__device__ int   g_cnt[N_MAX];      // out-count per src (CSR)
__device__ int   g_degi[N_MAX];     // in-count per dst
__device__ int   g_off[N_MAX];      // CSR row offsets
__device__ int   g_cursor[N_MAX];   // fill cursors (init = off)
__device__ int   g_partial[64];
__device__ int   g_edst[E_CAP];     // CSR column (dst) indices
__device__ float g_dinv[N_MAX];
__device__ float g_X[(size_t)N_MAX * F];
__device__ float g_Weff[F * F];     // beta * W  (identity handled in fp32 in-loop)

// ---------------------------------------------------------------------------
// cp.async helpers
__device__ __forceinline__ uint32_t smem_u32(const void* p) {
    return (uint32_t)__cvta_generic_to_shared(p);
}
__device__ __forceinline__ void cp_async16(uint32_t dst, const void* src, int src_bytes) {
    asm volatile("cp.async.cg.shared.global [%0], [%1], 16, %2;\n"
                 :: "r"(dst), "l"(src), "r"(src_bytes));
}
__device__ __forceinline__ void cp_commit() {
    asm volatile("cp.async.commit_group;\n" ::);
}
template <int N>
__device__ __forceinline__ void cp_wait() {
    asm volatile("cp.async.wait_group %0;\n" :: "n"(N));
}

__device__ __forceinline__ float beta_from(const float* lamda_p, const void* l_p) {
    float lam = __ldg(lamda_p);
    int   li  = *reinterpret_cast<const int*>(l_p);
    float lf  = (li > 0 && li < (1 << 20)) ? (float)li
                                           : *reinterpret_cast<const float*>(l_p);
    return logf(lam / lf + 1.0f);
}

// ---------------------------------------------------------------------------
// histogram (blocks [0, EB)) + Weff = beta*W (block EB)
__global__ void k_count_weff(const int* __restrict__ ei, int E, int EB,
                             const float* __restrict__ W,
                             const float* __restrict__ lamda_p,
                             const void* __restrict__ l_p) {
    if (blockIdx.x < EB) {
        int e = blockIdx.x * blockDim.x + threadIdx.x;
        if (e < E) {
            atomicAdd(&g_cnt[ei[e]], 1);
            atomicAdd(&g_degi[ei[E + e]], 1);
        }
    } else {
        float beta = beta_from(lamda_p, l_p);
        for (int idx = threadIdx.x; idx < F * F; idx += 256)
            g_Weff[idx] = beta * W[idx];
    }
}

// ---------------------------------------------------------------------------
// exclusive scan of g_cnt -> g_off (per-chunk), chunk totals to g_partial
__global__ void k_scan1(int n) {
    const int tid = threadIdx.x;
    const int base = blockIdx.x * SCAN_CHUNK;
    int v[8]; int s = 0;
#pragma unroll
    for (int j = 0; j < 8; j++) {
        int idx = base + tid * 8 + j;
        int c = (idx < n) ? g_cnt[idx] : 0;
        v[j] = s; s += c;
    }
    __shared__ int sh[256];
    sh[tid] = s;
    __syncthreads();
    for (int o = 1; o < 256; o <<= 1) {
        int t = (tid >= o) ? sh[tid - o] : 0;
        __syncthreads();
        sh[tid] += t;
        __syncthreads();
    }
    int excl = sh[tid] - s;
#pragma unroll
    for (int j = 0; j < 8; j++) {
        int idx = base + tid * 8 + j;
        if (idx < n) g_off[idx] = excl + v[j];
    }
    if (tid == 255) g_partial[blockIdx.x] = sh[255];
}

// ---------------------------------------------------------------------------
// fused: partial-scan (redundant per block, nb<=32) + offsets + cursors + dinv
__global__ void k_scan3_node(int n) {
    __shared__ int s_add;
    int chunk = blockIdx.x >> 3;           // 2048 / 256
    if (threadIdx.x < 32) {
        int x = (threadIdx.x < chunk) ? g_partial[threadIdx.x] : 0;
#pragma unroll
        for (int o = 16; o > 0; o >>= 1) x += __shfl_xor_sync(0xffffffffu, x, o);
        if (threadIdx.x == 0) s_add = x;
    }
    __syncthreads();
    int i = blockIdx.x * blockDim.x + threadIdx.x;
    if (i < n) {
        int off = g_off[i] + s_add;
        g_off[i]    = off;
        g_cursor[i] = off;
        float d = (float)g_degi[i] + 1.0f;
        g_dinv[i] = rsqrtf(d);
    }
}

// ---------------------------------------------------------------------------
// CSR fill
__global__ void k_fill(const int* __restrict__ ei, int E) {
    int e = blockIdx.x * blockDim.x + threadIdx.x;
    if (e < E) {
        int pos = atomicAdd(&g_cursor[ei[e]], 1);
        g_edst[pos] = ei[E + e];
    }
}

// ---------------------------------------------------------------------------
// fused aggregate + init: 2 warps per node, 4-edge unroll.
// X[i] = (1-a)*(dinv[i]*sum_j H[j]*dinv[j] + H[i]*dinv[i]^2) + a*H0[i]
__global__ __launch_bounds__(256)
void k_agg(const float* __restrict__ H,
           const float* __restrict__ H0,
           const float* __restrict__ alpha_p, int n)
{
    int gw   = (blockIdx.x * blockDim.x + threadIdx.x) >> 5;
    int node = gw >> 1;
    if (node >= n) return;
    int half = gw & 1;
    int lane = threadIdx.x & 31;
    int coff = half * 32 + lane;

    const int base = g_off[node];
    const int cnt  = g_cnt[node];

    const float4* H4 = reinterpret_cast<const float4*>(H);
    float4 acc = make_float4(0.f, 0.f, 0.f, 0.f);

    int e = 0;
    for (; e + 4 <= cnt; e += 4) {
        int d0 = __ldg(&g_edst[base + e]);
        int d1 = __ldg(&g_edst[base + e + 1]);
        int d2 = __ldg(&g_edst[base + e + 2]);
        int d3 = __ldg(&g_edst[base + e + 3]);
        float w0 = __ldg(&g_dinv[d0]);
        float w1 = __ldg(&g_dinv[d1]);
        float w2 = __ldg(&g_dinv[d2]);
        float w3 = __ldg(&g_dinv[d3]);
        float4 v0 = __ldg(H4 + (size_t)d0 * 64 + coff);
        float4 v1 = __ldg(H4 + (size_t)d1 * 64 + coff);
        float4 v2 = __ldg(H4 + (size_t)d2 * 64 + coff);
        float4 v3 = __ldg(H4 + (size_t)d3 * 64 + coff);
        acc.x += v0.x * w0 + v1.x * w1 + v2.x * w2 + v3.x * w3;
        acc.y += v0.y * w0 + v1.y * w1 + v2.y * w2 + v3.y * w3;
        acc.z += v0.z * w0 + v1.z * w1 + v2.z * w2 + v3.z * w3;
        acc.w += v0.w * w0 + v1.w * w1 + v2.w * w2 + v3.w * w3;
    }
    for (; e < cnt; e++) {
        int d0 = __ldg(&g_edst[base + e]);
        float w0 = __ldg(&g_dinv[d0]);
        float4 v0 = __ldg(H4 + (size_t)d0 * 64 + coff);
        acc.x += v0.x * w0; acc.y += v0.y * w0;
        acc.z += v0.z * w0; acc.w += v0.w * w0;
    }

    float a  = __ldg(alpha_p);
    float oa = 1.0f - a;
    float di = g_dinv[node];
    float id = di * di;
    size_t ro = (size_t)node * 64 + coff;
    float4 h = __ldg(H4 + ro);
    float4 z = __ldg(reinterpret_cast<const float4*>(H0) + ro);
    float4 r;
    r.x = oa * (di * acc.x + h.x * id) + a * z.x;
    r.y = oa * (di * acc.y + h.y * id) + a * z.y;
    r.z = oa * (di * acc.z + h.z * id) + a * z.z;
    r.w = oa * (di * acc.w + h.w * id) + a * z.w;
    reinterpret_cast<float4*>(g_X)[ro] = r;
}

// ---------------------------------------------------------------------------
// out = (1-beta)*X + X @ (beta*W).
// tf32 MMA for the W term; the dominant (1-beta)*X term is added in fp32
// straight from the A smem tile during the matching K-iteration.
// Block 128x256 (full N), 512 threads = 16 warps (4M x 4N), warp tile 32x64.
#define XS_STRIDE 36
#define BS_STRIDE 264
#define XS_ELEMS (128 * XS_STRIDE)
#define BS_ELEMS (32 * BS_STRIDE)
#define STAGE_ELEMS (XS_ELEMS + BS_ELEMS)
#define GEMM_SMEM_BYTES (2 * STAGE_ELEMS * 4)

__global__ __launch_bounds__(512, 1)
void k_gemm_tf32(float* __restrict__ out,
                 const float* __restrict__ lamda_p,
                 const void* __restrict__ l_p, int M)
{
    extern __shared__ float smem[];
    float* Xs[2] = { smem, smem + STAGE_ELEMS };
    float* Bs[2] = { smem + XS_ELEMS, smem + STAGE_ELEMS + XS_ELEMS };

    const int tid   = threadIdx.x;
    const int warp  = tid >> 5;
    const int lane  = tid & 31;
    const int gid   = lane >> 2;
    const int ln4   = lane & 3;
    const int warpM = warp & 3;   // 0..3
    const int warpN = warp >> 2;  // 0..3
    const int blockRow = blockIdx.x * 128;

    const float obeta = 1.0f - beta_from(lamda_p, l_p);

    float acc[2][8][4];
#pragma unroll
    for (int a = 0; a < 2; a++)
#pragma unroll
        for (int b = 0; b < 8; b++)
#pragma unroll
            for (int c = 0; c < 4; c++) acc[a][b][c] = 0.0f;

    auto prefetch = [&](int kt, int st) {
        int k0 = kt * 32;
#pragma unroll
        for (int i = 0; i < 2; i++) {          // A: 128x8 float4 = 1024
            int idx = tid + i * 512;
            int r = idx >> 3, c4 = idx & 7;
            int grow = blockRow + r;
            uint32_t dst = smem_u32(&Xs[st][r * XS_STRIDE + c4 * 4]);
            const void* src = &g_X[(size_t)(grow < M ? grow : 0) * F + k0 + c4 * 4];
            cp_async16(dst, src, grow < M ? 16 : 0);
        }
#pragma unroll
        for (int i = 0; i < 4; i++) {          // B: 32x64 float4 = 2048
            int idx = tid + i * 512;
            int r = idx >> 6, c4 = idx & 63;
            uint32_t dst = smem_u32(&Bs[st][r * BS_STRIDE + c4 * 4]);
            const void* src = &g_Weff[(size_t)(k0 + r) * F + c4 * 4];
            cp_async16(dst, src, 16);
        }
        cp_commit();
    };

    prefetch(0, 0);

#pragma unroll
    for (int kt = 0; kt < 8; kt++) {
        int st = kt & 1;
        if (kt + 1 < 8) {
            prefetch(kt + 1, st ^ 1);
            cp_wait<1>();
        } else {
            cp_wait<0>();
        }
        __syncthreads();

        const float* Xc = Xs[st];
        const float* Bc = Bs[st];
#pragma unroll
        for (int ks = 0; ks < 32; ks += 8) {
            uint32_t afr[2][4];
#pragma unroll
            for (int mt = 0; mt < 2; mt++) {
                int r0 = warpM * 32 + mt * 16 + gid;
                afr[mt][0] = __float_as_uint(Xc[r0 * XS_STRIDE + ks + ln4]);
                afr[mt][1] = __float_as_uint(Xc[(r0 + 8) * XS_STRIDE + ks + ln4]);
                afr[mt][2] = __float_as_uint(Xc[r0 * XS_STRIDE + ks + ln4 + 4]);
                afr[mt][3] = __float_as_uint(Xc[(r0 + 8) * XS_STRIDE + ks + ln4 + 4]);
            }
#pragma unroll
            for (int nt = 0; nt < 8; nt++) {
                int c0 = warpN * 64 + nt * 8 + gid;
                uint32_t b0 = __float_as_uint(Bc[(ks + ln4) * BS_STRIDE + c0]);
                uint32_t b1 = __float_as_uint(Bc[(ks + ln4 + 4) * BS_STRIDE + c0]);
#pragma unroll
                for (int mt = 0; mt < 2; mt++) {
                    asm volatile(
                        "mma.sync.aligned.m16n8k8.row.col.f32.tf32.tf32.f32 "
                        "{%0,%1,%2,%3}, {%4,%5,%6,%7}, {%8,%9}, {%0,%1,%2,%3};\n"
                        : "+f"(acc[mt][nt][0]), "+f"(acc[mt][nt][1]),
                          "+f"(acc[mt][nt][2]), "+f"(acc[mt][nt][3])
                        : "r"(afr[mt][0]), "r"(afr[mt][1]),
                          "r"(afr[mt][2]), "r"(afr[mt][3]),
                          "r"(b0), "r"(b1));
                }
            }
        }

        // fp32 identity term: this warp's output cols [warpN*64, warpN*64+64)
        // live in K-iterations kt = 2*warpN (+0) and 2*warpN+1 (+1).
        if ((kt >> 1) == warpN) {
            int ntbase = (kt & 1) * 4;
#pragma unroll
            for (int mt = 0; mt < 2; mt++) {
#pragma unroll
                for (int half = 0; half < 2; half++) {
                    int r0 = warpM * 32 + mt * 16 + gid + half * 8;
#pragma unroll
                    for (int j = 0; j < 4; j++) {
                        int nt = ntbase + j;
                        int k = nt * 8 + 2 * ln4 - (kt & 1) * 32;
                        acc[mt][nt][half * 2 + 0] += obeta * Xc[r0 * XS_STRIDE + k];
                        acc[mt][nt][half * 2 + 1] += obeta * Xc[r0 * XS_STRIDE + k + 1];
                    }
                }
            }
        }
        __syncthreads();
    }

    // epilogue: out = acc
#pragma unroll
    for (int mt = 0; mt < 2; mt++) {
#pragma unroll
        for (int half = 0; half < 2; half++) {
            int row = blockRow + warpM * 32 + mt * 16 + gid + half * 8;
            if (row >= M) continue;
#pragma unroll
            for (int nt = 0; nt < 8; nt++) {
                int col = warpN * 64 + nt * 8 + 2 * ln4;
                float2 o = make_float2(acc[mt][nt][half * 2 + 0],
                                       acc[mt][nt][half * 2 + 1]);
                *reinterpret_cast<float2*>(&out[(size_t)row * F + col]) = o;
            }
        }
    }
}

// ---------------------------------------------------------------------------
extern "C" void kernel_launch(void* const* d_in, const int* in_sizes, int n_in,
                              void* d_out, int out_size) {
    const float* H     = (const float*)d_in[0];
    const int*   ei    = (const int*)d_in[1];
    const float* H0    = (const float*)d_in[2];
    const float* W     = (const float*)d_in[3];
    const float* lamda = (const float*)d_in[4];
    const float* alpha = (const float*)d_in[5];
    const void*  lp    = d_in[6];
    float* out = (float*)d_out;

    const int n = in_sizes[0] / F;   // 50000
    const int E = in_sizes[1] / 2;   // 800000
    const int nScanBlocks = (n + SCAN_CHUNK - 1) / SCAN_CHUNK;
    const int EB = (E + 255) / 256;

    void* p_cnt = nullptr; void* p_degi = nullptr;
    cudaGetSymbolAddress(&p_cnt, g_cnt);
    cudaGetSymbolAddress(&p_degi, g_degi);
    cudaMemsetAsync(p_cnt, 0, (size_t)n * sizeof(int), 0);
    cudaMemsetAsync(p_degi, 0, (size_t)n * sizeof(int), 0);

    cudaFuncSetAttribute(k_gemm_tf32,
                         cudaFuncAttributeMaxDynamicSharedMemorySize,
                         GEMM_SMEM_BYTES);

    k_count_weff<<<EB + 1, 256>>>(ei, E, EB, W, lamda, lp);
    k_scan1<<<nScanBlocks, 256>>>(n);
    k_scan3_node<<<(n + 255) / 256, 256>>>(n);
    k_fill <<<(E + 255) / 256, 256>>>(ei, E);

    long long agg_threads = (long long)n * 64;   // 2 warps per node
    k_agg<<<(int)((agg_threads + 255) / 256), 256>>>(H, H0, alpha, n);

    k_gemm_tf32<<<(n + 127) / 128, 512, GEMM_SMEM_BYTES>>>(out, lamda, lp, n);
}

// round 7
// speedup vs baseline: 1.0586x; 1.0586x over previous
#include <cuda_runtime.h>
#include <cuda_fp16.h>
#include <math.h>
#include <stdint.h>

#define F 256
#define N_MAX 65536
#define E_CAP (1 << 20)
#define SCAN_CHUNK 2048

// Scratch (allocation-free rule: __device__ globals)
__device__ int   g_cnt[N_MAX];      // out-count per src (CSR)
__device__ int   g_degi[N_MAX];     // in-count per dst
__device__ int   g_off[N_MAX];      // CSR row offsets
__device__ int   g_cursor[N_MAX];   // fill cursors (init = off)
__device__ int   g_partial[64];
__device__ int   g_edst[E_CAP];     // CSR column (dst) indices
__device__ float g_dinv[N_MAX];
__device__ float g_X[(size_t)N_MAX * F];
__device__ float g_Weff[F * F];               // beta * W
__device__ uint4 g_H16[(size_t)N_MAX * F / 8]; // fp16(H[j]*dinv[j]), 8 halves per uint4

// ---------------------------------------------------------------------------
// cp.async helpers
__device__ __forceinline__ uint32_t smem_u32(const void* p) {
    return (uint32_t)__cvta_generic_to_shared(p);
}
__device__ __forceinline__ void cp_async16(uint32_t dst, const void* src, int src_bytes) {
    asm volatile("cp.async.cg.shared.global [%0], [%1], 16, %2;\n"
                 :: "r"(dst), "l"(src), "r"(src_bytes));
}
__device__ __forceinline__ void cp_commit() {
    asm volatile("cp.async.commit_group;\n" ::);
}
template <int N>
__device__ __forceinline__ void cp_wait() {
    asm volatile("cp.async.wait_group %0;\n" :: "n"(N));
}

__device__ __forceinline__ float beta_from(const float* lamda_p, const void* l_p) {
    float lam = __ldg(lamda_p);
    int   li  = *reinterpret_cast<const int*>(l_p);
    float lf  = (li > 0 && li < (1 << 20)) ? (float)li
                                           : *reinterpret_cast<const float*>(l_p);
    return logf(lam / lf + 1.0f);
}

// ---------------------------------------------------------------------------
// histogram (blocks [0, EB)) + Weff = beta*W (block EB)
__global__ void k_count_weff(const int* __restrict__ ei, int E, int EB,
                             const float* __restrict__ W,
                             const float* __restrict__ lamda_p,
                             const void* __restrict__ l_p) {
    if (blockIdx.x < EB) {
        int e = blockIdx.x * blockDim.x + threadIdx.x;
        if (e < E) {
            atomicAdd(&g_cnt[ei[e]], 1);
            atomicAdd(&g_degi[ei[E + e]], 1);
        }
    } else {
        float beta = beta_from(lamda_p, l_p);
        for (int idx = threadIdx.x; idx < F * F; idx += 256)
            g_Weff[idx] = beta * W[idx];
    }
}

// ---------------------------------------------------------------------------
// exclusive scan of g_cnt -> g_off (per-chunk), chunk totals to g_partial
__global__ void k_scan1(int n) {
    const int tid = threadIdx.x;
    const int base = blockIdx.x * SCAN_CHUNK;
    int v[8]; int s = 0;
#pragma unroll
    for (int j = 0; j < 8; j++) {
        int idx = base + tid * 8 + j;
        int c = (idx < n) ? g_cnt[idx] : 0;
        v[j] = s; s += c;
    }
    __shared__ int sh[256];
    sh[tid] = s;
    __syncthreads();
    for (int o = 1; o < 256; o <<= 1) {
        int t = (tid >= o) ? sh[tid - o] : 0;
        __syncthreads();
        sh[tid] += t;
        __syncthreads();
    }
    int excl = sh[tid] - s;
#pragma unroll
    for (int j = 0; j < 8; j++) {
        int idx = base + tid * 8 + j;
        if (idx < n) g_off[idx] = excl + v[j];
    }
    if (tid == 255) g_partial[blockIdx.x] = sh[255];
}

// ---------------------------------------------------------------------------
// fused: partial-scan (redundant per block, nb<=32) + offsets + cursors + dinv
__global__ void k_scan3_node(int n) {
    __shared__ int s_add;
    int chunk = blockIdx.x >> 3;           // 2048 / 256
    if (threadIdx.x < 32) {
        int x = (threadIdx.x < chunk) ? g_partial[threadIdx.x] : 0;
#pragma unroll
        for (int o = 16; o > 0; o >>= 1) x += __shfl_xor_sync(0xffffffffu, x, o);
        if (threadIdx.x == 0) s_add = x;
    }
    __syncthreads();
    int i = blockIdx.x * blockDim.x + threadIdx.x;
    if (i < n) {
        int off = g_off[i] + s_add;
        g_off[i]    = off;
        g_cursor[i] = off;
        float d = (float)g_degi[i] + 1.0f;
        g_dinv[i] = rsqrtf(d);
    }
}

// ---------------------------------------------------------------------------
// fused: CSR fill (blocks [0,EB)) + H16 = fp16(H * dinv) (blocks [EB, EB+HB))
__global__ void k_fill_h16(const int* __restrict__ ei, int E, int EB,
                           const float* __restrict__ H, int n) {
    if (blockIdx.x < EB) {
        int e = blockIdx.x * blockDim.x + threadIdx.x;
        if (e < E) {
            int pos = atomicAdd(&g_cursor[ei[e]], 1);
            g_edst[pos] = ei[E + e];
        }
    } else {
        int t = (blockIdx.x - EB) * blockDim.x + threadIdx.x;  // one per 8 floats
        if (t < n * 32) {
            int node = t >> 5;                // 32 threads per node row
            float di = __ldg(&g_dinv[node]);
            const float4* Hp = reinterpret_cast<const float4*>(H) + (size_t)t * 2;
            float4 a = __ldg(Hp), b = __ldg(Hp + 1);
            __half2 p0 = __floats2half2_rn(a.x * di, a.y * di);
            __half2 p1 = __floats2half2_rn(a.z * di, a.w * di);
            __half2 p2 = __floats2half2_rn(b.x * di, b.y * di);
            __half2 p3 = __floats2half2_rn(b.z * di, b.w * di);
            uint4 o;
            o.x = *reinterpret_cast<uint32_t*>(&p0);
            o.y = *reinterpret_cast<uint32_t*>(&p1);
            o.z = *reinterpret_cast<uint32_t*>(&p2);
            o.w = *reinterpret_cast<uint32_t*>(&p3);
            g_H16[t] = o;
        }
    }
}

// ---------------------------------------------------------------------------
// fused aggregate + init: 1 warp per node, fp16 gather, fp32 accumulate.
// X[i] = (1-a)*(dinv[i]*sum_j H16[j] + H[i]*dinv[i]^2) + a*H0[i]
__device__ __forceinline__ void acc8(float* acc, uint4 v) {
    float2 f0 = __half22float2(*reinterpret_cast<__half2*>(&v.x));
    float2 f1 = __half22float2(*reinterpret_cast<__half2*>(&v.y));
    float2 f2 = __half22float2(*reinterpret_cast<__half2*>(&v.z));
    float2 f3 = __half22float2(*reinterpret_cast<__half2*>(&v.w));
    acc[0] += f0.x; acc[1] += f0.y;
    acc[2] += f1.x; acc[3] += f1.y;
    acc[4] += f2.x; acc[5] += f2.y;
    acc[6] += f3.x; acc[7] += f3.y;
}

__global__ __launch_bounds__(256)
void k_agg(const float* __restrict__ H,
           const float* __restrict__ H0,
           const float* __restrict__ alpha_p, int n)
{
    int node = (blockIdx.x * blockDim.x + threadIdx.x) >> 5;
    if (node >= n) return;
    int lane = threadIdx.x & 31;

    const int base = g_off[node];
    const int cnt  = g_cnt[node];

    float acc[8];
#pragma unroll
    for (int j = 0; j < 8; j++) acc[j] = 0.0f;

    int e = 0;
    for (; e + 4 <= cnt; e += 4) {
        int d0 = __ldg(&g_edst[base + e]);
        int d1 = __ldg(&g_edst[base + e + 1]);
        int d2 = __ldg(&g_edst[base + e + 2]);
        int d3 = __ldg(&g_edst[base + e + 3]);
        uint4 v0 = __ldg(&g_H16[(size_t)d0 * 32 + lane]);
        uint4 v1 = __ldg(&g_H16[(size_t)d1 * 32 + lane]);
        uint4 v2 = __ldg(&g_H16[(size_t)d2 * 32 + lane]);
        uint4 v3 = __ldg(&g_H16[(size_t)d3 * 32 + lane]);
        acc8(acc, v0); acc8(acc, v1); acc8(acc, v2); acc8(acc, v3);
    }
    for (; e < cnt; e++) {
        int d0 = __ldg(&g_edst[base + e]);
        uint4 v0 = __ldg(&g_H16[(size_t)d0 * 32 + lane]);
        acc8(acc, v0);
    }

    float a  = __ldg(alpha_p);
    float oa = 1.0f - a;
    float di = g_dinv[node];
    float id = di * di;
    size_t ro = (size_t)node * 64 + lane * 2;   // float4 index
    const float4* H4  = reinterpret_cast<const float4*>(H);
    const float4* H04 = reinterpret_cast<const float4*>(H0);
    float4 h0 = __ldg(H4 + ro),  h1 = __ldg(H4 + ro + 1);
    float4 z0 = __ldg(H04 + ro), z1 = __ldg(H04 + ro + 1);
    float4 r0, r1;
    r0.x = oa * (di * acc[0] + h0.x * id) + a * z0.x;
    r0.y = oa * (di * acc[1] + h0.y * id) + a * z0.y;
    r0.z = oa * (di * acc[2] + h0.z * id) + a * z0.z;
    r0.w = oa * (di * acc[3] + h0.w * id) + a * z0.w;
    r1.x = oa * (di * acc[4] + h1.x * id) + a * z1.x;
    r1.y = oa * (di * acc[5] + h1.y * id) + a * z1.y;
    r1.z = oa * (di * acc[6] + h1.z * id) + a * z1.z;
    r1.w = oa * (di * acc[7] + h1.w * id) + a * z1.w;
    float4* X4 = reinterpret_cast<float4*>(g_X);
    X4[ro]     = r0;
    X4[ro + 1] = r1;
}

// ---------------------------------------------------------------------------
// out = (1-beta)*X + X @ (beta*W).  tf32 MMA mainloop (clean, no extra state);
// fp32 identity term added in the epilogue from a global re-read of X.
// Block 128x256 (full N), 512 threads = 16 warps (4M x 4N), warp tile 32x64.
#define XS_STRIDE 36
#define BS_STRIDE 264
#define XS_ELEMS (128 * XS_STRIDE)
#define BS_ELEMS (32 * BS_STRIDE)
#define STAGE_ELEMS (XS_ELEMS + BS_ELEMS)
#define GEMM_SMEM_BYTES (2 * STAGE_ELEMS * 4)

__global__ __launch_bounds__(512, 1)
void k_gemm_tf32(float* __restrict__ out,
                 const float* __restrict__ lamda_p,
                 const void* __restrict__ l_p, int M)
{
    extern __shared__ float smem[];
    float* Xs[2] = { smem, smem + STAGE_ELEMS };
    float* Bs[2] = { smem + XS_ELEMS, smem + STAGE_ELEMS + XS_ELEMS };

    const int tid   = threadIdx.x;
    const int warp  = tid >> 5;
    const int lane  = tid & 31;
    const int gid   = lane >> 2;
    const int ln4   = lane & 3;
    const int warpM = warp & 3;   // 0..3
    const int warpN = warp >> 2;  // 0..3
    const int blockRow = blockIdx.x * 128;

    float acc[2][8][4];
#pragma unroll
    for (int a = 0; a < 2; a++)
#pragma unroll
        for (int b = 0; b < 8; b++)
#pragma unroll
            for (int c = 0; c < 4; c++) acc[a][b][c] = 0.0f;

    auto prefetch = [&](int kt, int st) {
        int k0 = kt * 32;
#pragma unroll
        for (int i = 0; i < 2; i++) {          // A: 128x8 float4 = 1024
            int idx = tid + i * 512;
            int r = idx >> 3, c4 = idx & 7;
            int grow = blockRow + r;
            uint32_t dst = smem_u32(&Xs[st][r * XS_STRIDE + c4 * 4]);
            const void* src = &g_X[(size_t)(grow < M ? grow : 0) * F + k0 + c4 * 4];
            cp_async16(dst, src, grow < M ? 16 : 0);
        }
#pragma unroll
        for (int i = 0; i < 4; i++) {          // B: 32x64 float4 = 2048
            int idx = tid + i * 512;
            int r = idx >> 6, c4 = idx & 63;
            uint32_t dst = smem_u32(&Bs[st][r * BS_STRIDE + c4 * 4]);
            const void* src = &g_Weff[(size_t)(k0 + r) * F + c4 * 4];
            cp_async16(dst, src, 16);
        }
        cp_commit();
    };

    prefetch(0, 0);

#pragma unroll
    for (int kt = 0; kt < 8; kt++) {
        int st = kt & 1;
        if (kt + 1 < 8) {
            prefetch(kt + 1, st ^ 1);
            cp_wait<1>();
        } else {
            cp_wait<0>();
        }
        __syncthreads();

        const float* Xc = Xs[st];
        const float* Bc = Bs[st];
#pragma unroll
        for (int ks = 0; ks < 32; ks += 8) {
            uint32_t afr[2][4];
#pragma unroll
            for (int mt = 0; mt < 2; mt++) {
                int r0 = warpM * 32 + mt * 16 + gid;
                afr[mt][0] = __float_as_uint(Xc[r0 * XS_STRIDE + ks + ln4]);
                afr[mt][1] = __float_as_uint(Xc[(r0 + 8) * XS_STRIDE + ks + ln4]);
                afr[mt][2] = __float_as_uint(Xc[r0 * XS_STRIDE + ks + ln4 + 4]);
                afr[mt][3] = __float_as_uint(Xc[(r0 + 8) * XS_STRIDE + ks + ln4 + 4]);
            }
#pragma unroll
            for (int nt = 0; nt < 8; nt++) {
                int c0 = warpN * 64 + nt * 8 + gid;
                uint32_t b0 = __float_as_uint(Bc[(ks + ln4) * BS_STRIDE + c0]);
                uint32_t b1 = __float_as_uint(Bc[(ks + ln4 + 4) * BS_STRIDE + c0]);
#pragma unroll
                for (int mt = 0; mt < 2; mt++) {
                    asm volatile(
                        "mma.sync.aligned.m16n8k8.row.col.f32.tf32.tf32.f32 "
                        "{%0,%1,%2,%3}, {%4,%5,%6,%7}, {%8,%9}, {%0,%1,%2,%3};\n"
                        : "+f"(acc[mt][nt][0]), "+f"(acc[mt][nt][1]),
                          "+f"(acc[mt][nt][2]), "+f"(acc[mt][nt][3])
                        : "r"(afr[mt][0]), "r"(afr[mt][1]),
                          "r"(afr[mt][2]), "r"(afr[mt][3]),
                          "r"(b0), "r"(b1));
                }
            }
        }
        __syncthreads();
    }

    // epilogue: out = (1-beta)*X (fp32 from global) + acc
    const float obeta = 1.0f - beta_from(lamda_p, l_p);
#pragma unroll
    for (int mt = 0; mt < 2; mt++) {
#pragma unroll
        for (int half = 0; half < 2; half++) {
            int row = blockRow + warpM * 32 + mt * 16 + gid + half * 8;
            if (row >= M) continue;
#pragma unroll
            for (int nt = 0; nt < 8; nt++) {
                int col = warpN * 64 + nt * 8 + 2 * ln4;
                float2 xv = *reinterpret_cast<const float2*>(&g_X[(size_t)row * F + col]);
                float2 o;
                o.x = obeta * xv.x + acc[mt][nt][half * 2 + 0];
                o.y = obeta * xv.y + acc[mt][nt][half * 2 + 1];
                *reinterpret_cast<float2*>(&out[(size_t)row * F + col]) = o;
            }
        }
    }
}

// ---------------------------------------------------------------------------
extern "C" void kernel_launch(void* const* d_in, const int* in_sizes, int n_in,
                              void* d_out, int out_size) {
    const float* H     = (const float*)d_in[0];
    const int*   ei    = (const int*)d_in[1];
    const float* H0    = (const float*)d_in[2];
    const float* W     = (const float*)d_in[3];
    const float* lamda = (const float*)d_in[4];
    const float* alpha = (const float*)d_in[5];
    const void*  lp    = d_in[6];
    float* out = (float*)d_out;

    const int n = in_sizes[0] / F;   // 50000
    const int E = in_sizes[1] / 2;   // 800000
    const int nScanBlocks = (n + SCAN_CHUNK - 1) / SCAN_CHUNK;
    const int EB = (E + 255) / 256;
    const int HB = (n * 32 + 255) / 256;   // h16 conversion blocks

    void* p_cnt = nullptr; void* p_degi = nullptr;
    cudaGetSymbolAddress(&p_cnt, g_cnt);
    cudaGetSymbolAddress(&p_degi, g_degi);
    cudaMemsetAsync(p_cnt, 0, (size_t)n * sizeof(int), 0);
    cudaMemsetAsync(p_degi, 0, (size_t)n * sizeof(int), 0);

    cudaFuncSetAttribute(k_gemm_tf32,
                         cudaFuncAttributeMaxDynamicSharedMemorySize,
                         GEMM_SMEM_BYTES);

    k_count_weff<<<EB + 1, 256>>>(ei, E, EB, W, lamda, lp);
    k_scan1<<<nScanBlocks, 256>>>(n);
    k_scan3_node<<<(n + 255) / 256, 256>>>(n);
    k_fill_h16<<<EB + HB, 256>>>(ei, E, EB, H, n);

    long long agg_threads = (long long)n * 32;   // 1 warp per node
    k_agg<<<(int)((agg_threads + 255) / 256), 256>>>(H, H0, alpha, n);

    k_gemm_tf32<<<(n + 127) / 128, 512, GEMM_SMEM_BYTES>>>(out, lamda, lp, n);
}

// round 8
// speedup vs baseline: 1.3156x; 1.2428x over previous
#include <cuda_runtime.h>
#include <cuda_fp16.h>
#include <cuda_bf16.h>
#include <math.h>
#include <stdint.h>

#define F 256
#define N_MAX 65536
#define E_CAP (1 << 20)
#define SCAN_CHUNK 2048

// Scratch (allocation-free rule: __device__ globals)
__device__ int   g_cnt2[2 * N_MAX]; // [0,N): src counts, [N_MAX,2N): dst degree
__device__ int   g_off[N_MAX];      // CSR row offsets
__device__ int   g_cursor[N_MAX];   // fill cursors (init = off)
__device__ int   g_partial[64];
__device__ int   g_edst[E_CAP];     // CSR column (dst) indices
__device__ float g_dinv[N_MAX];
__device__ float g_X[(size_t)N_MAX * F];                 // fp32 init_res
__device__ __nv_bfloat16 g_Xb[(size_t)N_MAX * F];        // bf16 init_res (MMA A)
__device__ __nv_bfloat16 g_Wt[F * F];                    // bf16 (beta*W)^T, [n][k]
__device__ uint4 g_H16[(size_t)N_MAX * F / 8];           // fp16(H[j]*dinv[j])

// ---------------------------------------------------------------------------
// cp.async helpers
__device__ __forceinline__ uint32_t smem_u32(const void* p) {
    return (uint32_t)__cvta_generic_to_shared(p);
}
__device__ __forceinline__ void cp_async16(uint32_t dst, const void* src, int src_bytes) {
    asm volatile("cp.async.cg.shared.global [%0], [%1], 16, %2;\n"
                 :: "r"(dst), "l"(src), "r"(src_bytes));
}
__device__ __forceinline__ void cp_commit() {
    asm volatile("cp.async.commit_group;\n" ::);
}
template <int N>
__device__ __forceinline__ void cp_wait() {
    asm volatile("cp.async.wait_group %0;\n" :: "n"(N));
}

__device__ __forceinline__ float beta_from(const float* lamda_p, const void* l_p) {
    float lam = __ldg(lamda_p);
    int   li  = *reinterpret_cast<const int*>(l_p);
    float lf  = (li > 0 && li < (1 << 20)) ? (float)li
                                           : *reinterpret_cast<const float*>(l_p);
    return logf(lam / lf + 1.0f);
}

// ---------------------------------------------------------------------------
// histogram (blocks [0, EB)) + Wt = bf16((beta*W)^T) (blocks [EB, EB+16))
__global__ void k_count_weff(const int* __restrict__ ei, int E, int EB,
                             const float* __restrict__ W,
                             const float* __restrict__ lamda_p,
                             const void* __restrict__ l_p) {
    if (blockIdx.x < EB) {
        int e = blockIdx.x * blockDim.x + threadIdx.x;
        if (e < E) {
            atomicAdd(&g_cnt2[ei[e]], 1);
            atomicAdd(&g_cnt2[N_MAX + ei[E + e]], 1);
        }
    } else {
        float beta = beta_from(lamda_p, l_p);
        int b = blockIdx.x - EB;                 // 0..15
        int start = b * 4096;
        for (int t = threadIdx.x; t < 4096; t += 256) {
            int idx = start + t;                 // n*256 + k
            int nn = idx >> 8, kk = idx & 255;
            g_Wt[idx] = __float2bfloat16(beta * W[kk * F + nn]);
        }
    }
}

// ---------------------------------------------------------------------------
// exclusive scan of src counts -> g_off (per-chunk), chunk totals to g_partial
__global__ void k_scan1(int n) {
    const int tid = threadIdx.x;
    const int base = blockIdx.x * SCAN_CHUNK;
    int v[8]; int s = 0;
#pragma unroll
    for (int j = 0; j < 8; j++) {
        int idx = base + tid * 8 + j;
        int c = (idx < n) ? g_cnt2[idx] : 0;
        v[j] = s; s += c;
    }
    __shared__ int sh[256];
    sh[tid] = s;
    __syncthreads();
    for (int o = 1; o < 256; o <<= 1) {
        int t = (tid >= o) ? sh[tid - o] : 0;
        __syncthreads();
        sh[tid] += t;
        __syncthreads();
    }
    int excl = sh[tid] - s;
#pragma unroll
    for (int j = 0; j < 8; j++) {
        int idx = base + tid * 8 + j;
        if (idx < n) g_off[idx] = excl + v[j];
    }
    if (tid == 255) g_partial[blockIdx.x] = sh[255];
}

// ---------------------------------------------------------------------------
// fused: partial-scan (redundant per block, nb<=32) + offsets + cursors + dinv
__global__ void k_scan3_node(int n) {
    __shared__ int s_add;
    int chunk = blockIdx.x >> 3;           // 2048 / 256
    if (threadIdx.x < 32) {
        int x = (threadIdx.x < chunk) ? g_partial[threadIdx.x] : 0;
#pragma unroll
        for (int o = 16; o > 0; o >>= 1) x += __shfl_xor_sync(0xffffffffu, x, o);
        if (threadIdx.x == 0) s_add = x;
    }
    __syncthreads();
    int i = blockIdx.x * blockDim.x + threadIdx.x;
    if (i < n) {
        int off = g_off[i] + s_add;
        g_off[i]    = off;
        g_cursor[i] = off;
        float d = (float)g_cnt2[N_MAX + i] + 1.0f;
        g_dinv[i] = rsqrtf(d);
    }
}

// ---------------------------------------------------------------------------
// fused: CSR fill (blocks [0,EB)) + H16 = fp16(H * dinv) (blocks [EB, EB+HB))
__global__ void k_fill_h16(const int* __restrict__ ei, int E, int EB,
                           const float* __restrict__ H, int n) {
    if (blockIdx.x < EB) {
        int e = blockIdx.x * blockDim.x + threadIdx.x;
        if (e < E) {
            int pos = atomicAdd(&g_cursor[ei[e]], 1);
            g_edst[pos] = ei[E + e];
        }
    } else {
        int t = (blockIdx.x - EB) * blockDim.x + threadIdx.x;  // one per 8 floats
        if (t < n * 32) {
            int node = t >> 5;
            float di = __ldg(&g_dinv[node]);
            const float4* Hp = reinterpret_cast<const float4*>(H) + (size_t)t * 2;
            float4 a = __ldg(Hp), b = __ldg(Hp + 1);
            __half2 p0 = __floats2half2_rn(a.x * di, a.y * di);
            __half2 p1 = __floats2half2_rn(a.z * di, a.w * di);
            __half2 p2 = __floats2half2_rn(b.x * di, b.y * di);
            __half2 p3 = __floats2half2_rn(b.z * di, b.w * di);
            uint4 o;
            o.x = *reinterpret_cast<uint32_t*>(&p0);
            o.y = *reinterpret_cast<uint32_t*>(&p1);
            o.z = *reinterpret_cast<uint32_t*>(&p2);
            o.w = *reinterpret_cast<uint32_t*>(&p3);
            g_H16[t] = o;
        }
    }
}

// ---------------------------------------------------------------------------
// fused aggregate + init: 1 warp per node, fp16 gather (8-edge unroll, MLP=8),
// fp32 accumulate. Writes fp32 X and bf16 Xb.
__device__ __forceinline__ void acc8(float* acc, uint4 v) {
    float2 f0 = __half22float2(*reinterpret_cast<__half2*>(&v.x));
    float2 f1 = __half22float2(*reinterpret_cast<__half2*>(&v.y));
    float2 f2 = __half22float2(*reinterpret_cast<__half2*>(&v.z));
    float2 f3 = __half22float2(*reinterpret_cast<__half2*>(&v.w));
    acc[0] += f0.x; acc[1] += f0.y;
    acc[2] += f1.x; acc[3] += f1.y;
    acc[4] += f2.x; acc[5] += f2.y;
    acc[6] += f3.x; acc[7] += f3.y;
}

__global__ __launch_bounds__(256)
void k_agg(const float* __restrict__ H,
           const float* __restrict__ H0,
           const float* __restrict__ alpha_p, int n)
{
    int node = (blockIdx.x * blockDim.x + threadIdx.x) >> 5;
    if (node >= n) return;
    int lane = threadIdx.x & 31;

    const int base = g_off[node];
    const int cnt  = g_cnt2[node];

    float acc[8];
#pragma unroll
    for (int j = 0; j < 8; j++) acc[j] = 0.0f;

    int e = 0;
    for (; e + 8 <= cnt; e += 8) {
        int d[8];
#pragma unroll
        for (int j = 0; j < 8; j++) d[j] = __ldg(&g_edst[base + e + j]);
        uint4 v[8];
#pragma unroll
        for (int j = 0; j < 8; j++) v[j] = __ldg(&g_H16[(size_t)d[j] * 32 + lane]);
#pragma unroll
        for (int j = 0; j < 8; j++) acc8(acc, v[j]);
    }
    for (; e < cnt; e++) {
        int d0 = __ldg(&g_edst[base + e]);
        uint4 v0 = __ldg(&g_H16[(size_t)d0 * 32 + lane]);
        acc8(acc, v0);
    }

    float a  = __ldg(alpha_p);
    float oa = 1.0f - a;
    float di = g_dinv[node];
    float id = di * di;
    size_t ro = (size_t)node * 64 + lane * 2;   // float4 index
    const float4* H4  = reinterpret_cast<const float4*>(H);
    const float4* H04 = reinterpret_cast<const float4*>(H0);
    float4 h0 = __ldg(H4 + ro),  h1 = __ldg(H4 + ro + 1);
    float4 z0 = __ldg(H04 + ro), z1 = __ldg(H04 + ro + 1);
    float4 r0, r1;
    r0.x = oa * (di * acc[0] + h0.x * id) + a * z0.x;
    r0.y = oa * (di * acc[1] + h0.y * id) + a * z0.y;
    r0.z = oa * (di * acc[2] + h0.z * id) + a * z0.z;
    r0.w = oa * (di * acc[3] + h0.w * id) + a * z0.w;
    r1.x = oa * (di * acc[4] + h1.x * id) + a * z1.x;
    r1.y = oa * (di * acc[5] + h1.y * id) + a * z1.y;
    r1.z = oa * (di * acc[6] + h1.z * id) + a * z1.z;
    r1.w = oa * (di * acc[7] + h1.w * id) + a * z1.w;
    float4* X4 = reinterpret_cast<float4*>(g_X);
    X4[ro]     = r0;
    X4[ro + 1] = r1;

    // bf16 copy for the MMA A operand
    __nv_bfloat162 b0 = __floats2bfloat162_rn(r0.x, r0.y);
    __nv_bfloat162 b1 = __floats2bfloat162_rn(r0.z, r0.w);
    __nv_bfloat162 b2 = __floats2bfloat162_rn(r1.x, r1.y);
    __nv_bfloat162 b3 = __floats2bfloat162_rn(r1.z, r1.w);
    uint4 ob;
    ob.x = *reinterpret_cast<uint32_t*>(&b0);
    ob.y = *reinterpret_cast<uint32_t*>(&b1);
    ob.z = *reinterpret_cast<uint32_t*>(&b2);
    ob.w = *reinterpret_cast<uint32_t*>(&b3);
    reinterpret_cast<uint4*>(g_Xb)[(size_t)node * 32 + lane] = ob;
}

// ---------------------------------------------------------------------------
// out = (1-beta)*X + Xb @ Wt^T   (bf16 m16n8k16 MMA; identity term fp32 in
// epilogue from g_X). Block 128x256, 512 threads = 16 warps (4M x 4N),
// warp tile 32x64, BK=32 (2 k16 steps), 2-stage cp.async.
#define AS_STRIDE 40                    // bf16 units; (20r+ln4) mod 32 bijective
#define BS_STRIDE 40
#define AS_ELEMS (128 * AS_STRIDE)
#define BS_ELEMS (256 * BS_STRIDE)
#define STAGE_ELEMS (AS_ELEMS + BS_ELEMS)
#define GEMM_SMEM_BYTES (2 * STAGE_ELEMS * 2)

__global__ __launch_bounds__(512, 1)
void k_gemm_bf16(float* __restrict__ out,
                 const float* __restrict__ lamda_p,
                 const void* __restrict__ l_p, int M)
{
    extern __shared__ __nv_bfloat16 smem[];
    __nv_bfloat16* As[2] = { smem, smem + STAGE_ELEMS };
    __nv_bfloat16* Bs[2] = { smem + AS_ELEMS, smem + STAGE_ELEMS + AS_ELEMS };

    const int tid   = threadIdx.x;
    const int warp  = tid >> 5;
    const int lane  = tid & 31;
    const int gid   = lane >> 2;
    const int ln4   = lane & 3;
    const int warpM = warp & 3;   // 0..3
    const int warpN = warp >> 2;  // 0..3
    const int blockRow = blockIdx.x * 128;

    float acc[2][8][4];
#pragma unroll
    for (int a = 0; a < 2; a++)
#pragma unroll
        for (int b = 0; b < 8; b++)
#pragma unroll
            for (int c = 0; c < 4; c++) acc[a][b][c] = 0.0f;

    auto prefetch = [&](int kt, int st) {
        int k0 = kt * 32;
        {   // A: 128 rows x 4 16B-chunks = 512 (1 per thread)
            int r = tid >> 2, c16 = tid & 3;
            int grow = blockRow + r;
            uint32_t dst = smem_u32(&As[st][r * AS_STRIDE + c16 * 8]);
            const void* src = &g_Xb[(size_t)(grow < M ? grow : 0) * F + k0 + c16 * 8];
            cp_async16(dst, src, grow < M ? 16 : 0);
        }
#pragma unroll
        for (int i = 0; i < 2; i++) {  // B: 256 n-rows x 4 chunks = 1024
            int idx = tid + i * 512;
            int r = idx >> 2, c16 = idx & 3;
            uint32_t dst = smem_u32(&Bs[st][r * BS_STRIDE + c16 * 8]);
            const void* src = &g_Wt[(size_t)r * F + k0 + c16 * 8];
            cp_async16(dst, src, 16);
        }
        cp_commit();
    };

    prefetch(0, 0);

#pragma unroll
    for (int kt = 0; kt < 8; kt++) {
        int st = kt & 1;
        if (kt + 1 < 8) {
            prefetch(kt + 1, st ^ 1);
            cp_wait<1>();
        } else {
            cp_wait<0>();
        }
        __syncthreads();

        const __nv_bfloat16* Ac = As[st];
        const __nv_bfloat16* Bc = Bs[st];
#pragma unroll
        for (int ks = 0; ks < 32; ks += 16) {
            uint32_t afr[2][4];
#pragma unroll
            for (int mt = 0; mt < 2; mt++) {
                int r0 = warpM * 32 + mt * 16 + gid;
                afr[mt][0] = *reinterpret_cast<const uint32_t*>(&Ac[r0 * AS_STRIDE + ks + 2 * ln4]);
                afr[mt][1] = *reinterpret_cast<const uint32_t*>(&Ac[(r0 + 8) * AS_STRIDE + ks + 2 * ln4]);
                afr[mt][2] = *reinterpret_cast<const uint32_t*>(&Ac[r0 * AS_STRIDE + ks + 8 + 2 * ln4]);
                afr[mt][3] = *reinterpret_cast<const uint32_t*>(&Ac[(r0 + 8) * AS_STRIDE + ks + 8 + 2 * ln4]);
            }
#pragma unroll
            for (int nt = 0; nt < 8; nt++) {
                int c0 = warpN * 64 + nt * 8 + gid;
                uint32_t b0 = *reinterpret_cast<const uint32_t*>(&Bc[c0 * BS_STRIDE + ks + 2 * ln4]);
                uint32_t b1 = *reinterpret_cast<const uint32_t*>(&Bc[c0 * BS_STRIDE + ks + 8 + 2 * ln4]);
#pragma unroll
                for (int mt = 0; mt < 2; mt++) {
                    asm volatile(
                        "mma.sync.aligned.m16n8k16.row.col.f32.bf16.bf16.f32 "
                        "{%0,%1,%2,%3}, {%4,%5,%6,%7}, {%8,%9}, {%0,%1,%2,%3};\n"
                        : "+f"(acc[mt][nt][0]), "+f"(acc[mt][nt][1]),
                          "+f"(acc[mt][nt][2]), "+f"(acc[mt][nt][3])
                        : "r"(afr[mt][0]), "r"(afr[mt][1]),
                          "r"(afr[mt][2]), "r"(afr[mt][3]),
                          "r"(b0), "r"(b1));
                }
            }
        }
        __syncthreads();
    }

    // epilogue: out = (1-beta)*X (fp32 from global) + acc
    const float obeta = 1.0f - beta_from(lamda_p, l_p);
#pragma unroll
    for (int mt = 0; mt < 2; mt++) {
#pragma unroll
        for (int half = 0; half < 2; half++) {
            int row = blockRow + warpM * 32 + mt * 16 + gid + half * 8;
            if (row >= M) continue;
#pragma unroll
            for (int nt = 0; nt < 8; nt++) {
                int col = warpN * 64 + nt * 8 + 2 * ln4;
                float2 xv = *reinterpret_cast<const float2*>(&g_X[(size_t)row * F + col]);
                float2 o;
                o.x = obeta * xv.x + acc[mt][nt][half * 2 + 0];
                o.y = obeta * xv.y + acc[mt][nt][half * 2 + 1];
                *reinterpret_cast<float2*>(&out[(size_t)row * F + col]) = o;
            }
        }
    }
}

// ---------------------------------------------------------------------------
extern "C" void kernel_launch(void* const* d_in, const int* in_sizes, int n_in,
                              void* d_out, int out_size) {
    const float* H     = (const float*)d_in[0];
    const int*   ei    = (const int*)d_in[1];
    const float* H0    = (const float*)d_in[2];
    const float* W     = (const float*)d_in[3];
    const float* lamda = (const float*)d_in[4];
    const float* alpha = (const float*)d_in[5];
    const void*  lp    = d_in[6];
    float* out = (float*)d_out;

    const int n = in_sizes[0] / F;   // 50000
    const int E = in_sizes[1] / 2;   // 800000
    const int nScanBlocks = (n + SCAN_CHUNK - 1) / SCAN_CHUNK;
    const int EB = (E + 255) / 256;
    const int HB = (n * 32 + 255) / 256;

    void* p_cnt2 = nullptr;
    cudaGetSymbolAddress(&p_cnt2, g_cnt2);
    cudaMemsetAsync(p_cnt2, 0, (size_t)2 * N_MAX * sizeof(int), 0);

    cudaFuncSetAttribute(k_gemm_bf16,
                         cudaFuncAttributeMaxDynamicSharedMemorySize,
                         GEMM_SMEM_BYTES);

    k_count_weff<<<EB + 16, 256>>>(ei, E, EB, W, lamda, lp);
    k_scan1<<<nScanBlocks, 256>>>(n);
    k_scan3_node<<<(n + 255) / 256, 256>>>(n);
    k_fill_h16<<<EB + HB, 256>>>(ei, E, EB, H, n);

    long long agg_threads = (long long)n * 32;   // 1 warp per node
    k_agg<<<(int)((agg_threads + 255) / 256), 256>>>(H, H0, alpha, n);

    k_gemm_bf16<<<(n + 127) / 128, 512, GEMM_SMEM_BYTES>>>(out, lamda, lp, n);
}